// round 1
// baseline (speedup 1.0000x reference)
#include <cuda_runtime.h>
#include <math.h>

// ---------------------------------------------------------------------------
// EmbedMatcher: neighbor GCN encode -> residual MLP + LayerNorm -> 4-step
// LSTM-with-support recurrence -> cosine similarity vs support vector.
//
// Key algebraic optimization: in the recurrence, h_r = [h, support_g] where
// support_g is row-invariant, so  h_r @ w_hh^T = h @ w_hh[:, :256]^T + rvec,
// rvec = w_hh[:, 256:] @ support_g  (computed once). Recurrent GEMM K: 512->256.
// ---------------------------------------------------------------------------

#define NTHREADS 256

// ---------------- scratch (no cudaMalloc allowed) ----------------
constexpr size_t N_BUFQ = 8192UL * 256;   // gather sums, query, row = b*2+side
constexpr size_t N_INVQ = 8192;
constexpr size_t N_BUFS = 16UL * 256;     // gather sums, support (10 rows used)
constexpr size_t N_INVS = 64;
constexpr size_t N_QNB  = 4096UL * 256;   // query_nb
constexpr size_t N_SNB  = 8UL * 256;      // support_nb (5 rows)
constexpr size_t N_HQ   = 4096UL * 512;
constexpr size_t N_HS   = 8UL * 512;
constexpr size_t N_ZQ   = 4096UL * 256;
constexpr size_t N_ZS   = 8UL * 256;
constexpr size_t N_QG   = 4096UL * 256;   // query_g (post-LN)
constexpr size_t N_SLN  = 8UL * 256;
constexpr size_t N_SG   = 256;            // support_g
constexpr size_t N_SN   = 256;            // normalized support_g
constexpr size_t N_XW   = 4096UL * 2048;
constexpr size_t N_ACC  = 4096UL * 2048;
constexpr size_t N_RV   = 2048;
constexpr size_t N_C    = 4096UL * 512;
constexpr size_t N_H    = 4096UL * 256;

constexpr size_t O_BUFQ = 0;
constexpr size_t O_INVQ = O_BUFQ + N_BUFQ;
constexpr size_t O_BUFS = O_INVQ + N_INVQ;
constexpr size_t O_INVS = O_BUFS + N_BUFS;
constexpr size_t O_QNB  = O_INVS + N_INVS;
constexpr size_t O_SNB  = O_QNB  + N_QNB;
constexpr size_t O_HQ   = O_SNB  + N_SNB;
constexpr size_t O_HS   = O_HQ   + N_HQ;
constexpr size_t O_ZQ   = O_HS   + N_HS;
constexpr size_t O_ZS   = O_ZQ   + N_ZQ;
constexpr size_t O_QG   = O_ZS   + N_ZS;
constexpr size_t O_SLN  = O_QG   + N_QG;
constexpr size_t O_SG   = O_SLN  + N_SLN;
constexpr size_t O_SN   = O_SG   + N_SG;
constexpr size_t O_XW   = O_SN   + N_SN;
constexpr size_t O_ACC  = O_XW   + N_XW;
constexpr size_t O_RV   = O_ACC  + N_ACC;
constexpr size_t O_C    = O_RV   + N_RV;
constexpr size_t O_H    = O_C    + N_C;
constexpr size_t SCRATCH_TOTAL = O_H + N_H;

__device__ float g_scratch[SCRATCH_TOTAL];

// ---------------- helpers ----------------
__device__ __forceinline__ float sigf(float x) { return 1.0f / (1.0f + expf(-x)); }

__device__ __forceinline__ float block_sum256(float v, float* sbuf) {
    int t = threadIdx.x;
    sbuf[t] = v;
    __syncthreads();
    #pragma unroll
    for (int s = 128; s > 0; s >>= 1) {
        if (t < s) sbuf[t] += sbuf[t + s];
        __syncthreads();
    }
    float r = sbuf[0];
    __syncthreads();
    return r;
}

// ---------------- gather + sum over 64 neighbors ----------------
// conn: (R, 64, 2) int32. Per row: sum emb[conn[n,0]][0..127] and emb[conn[n,1]].
// Output row = r*rowmul + rowoff; buf row layout [rel_sum(128) | ent_sum(128)].
__global__ void gather_sum_kernel(const int* __restrict__ conn,
                                  const int* __restrict__ deg,
                                  const float* __restrict__ emb,
                                  float* __restrict__ buf,
                                  float* __restrict__ invden,
                                  int rowmul, int rowoff)
{
    __shared__ int sc[128];
    int r = blockIdx.x;
    int t = threadIdx.x;  // 128 threads
    sc[t] = conn[r * 128 + t];
    __syncthreads();
    float s0 = 0.0f, s1 = 0.0f;
    #pragma unroll 4
    for (int n = 0; n < 64; n++) {
        s0 += __ldg(&emb[(size_t)sc[2 * n]     * 128 + t]);
        s1 += __ldg(&emb[(size_t)sc[2 * n + 1] * 128 + t]);
    }
    int row = r * rowmul + rowoff;
    buf[(size_t)row * 256 + t]       = s0;
    buf[(size_t)row * 256 + 128 + t] = s1;
    if (t == 0) invden[row] = 1.0f / (float)max(deg[r], 1);
}

// ---------------- generic "TN" SGEMM: C[m][n] = sum_k A[m][k]*B[n][k] --------
// A: (M,K) row-major lda; B: (N,K) row-major ldb (all weights stored this way).
// Tiles: 128x128x8, 8x8 per thread, 256 threads.
enum { EPI_RAW = 0, EPI_RELU = 1, EPI_RES = 2, EPI_NB = 3 };

template <int EPI>
__global__ __launch_bounds__(256, 2)
void gemm_tn(const float* __restrict__ A, int lda,
             const float* __restrict__ B, int ldb,
             float* __restrict__ C, int ldc,
             int M, int N, int K,
             const float* __restrict__ bias,
             const float* __restrict__ extra)
{
    __shared__ float As[8][132];
    __shared__ float Bs[8][132];
    const int tid  = threadIdx.x;
    const int bm   = blockIdx.y * 128;
    const int bn   = blockIdx.x * 128;
    const int lrow = tid >> 1;          // 0..127
    const int lcol = (tid & 1) << 2;    // 0 or 4
    const int ty   = tid >> 4;          // 0..15
    const int tx   = tid & 15;          // 0..15

    float acc[8][8];
    #pragma unroll
    for (int i = 0; i < 8; i++)
        #pragma unroll
        for (int j = 0; j < 8; j++) acc[i][j] = 0.0f;

    const bool arow_ok = (bm + lrow) < M;
    const float* Aptr = A + (size_t)(bm + lrow) * lda + lcol;
    const float* Bptr = B + (size_t)(bn + lrow) * ldb + lcol;  // N is mult of 128

    for (int k0 = 0; k0 < K; k0 += 8) {
        float4 av = make_float4(0.f, 0.f, 0.f, 0.f);
        if (arow_ok) av = *(const float4*)(Aptr + k0);
        float4 bv = *(const float4*)(Bptr + k0);
        __syncthreads();
        As[lcol + 0][lrow] = av.x; As[lcol + 1][lrow] = av.y;
        As[lcol + 2][lrow] = av.z; As[lcol + 3][lrow] = av.w;
        Bs[lcol + 0][lrow] = bv.x; Bs[lcol + 1][lrow] = bv.y;
        Bs[lcol + 2][lrow] = bv.z; Bs[lcol + 3][lrow] = bv.w;
        __syncthreads();
        #pragma unroll
        for (int kk = 0; kk < 8; kk++) {
            float ar[8], br[8];
            *(float4*)&ar[0] = *(const float4*)&As[kk][ty * 8];
            *(float4*)&ar[4] = *(const float4*)&As[kk][ty * 8 + 4];
            *(float4*)&br[0] = *(const float4*)&Bs[kk][tx * 8];
            *(float4*)&br[4] = *(const float4*)&Bs[kk][tx * 8 + 4];
            #pragma unroll
            for (int i = 0; i < 8; i++)
                #pragma unroll
                for (int j = 0; j < 8; j++)
                    acc[i][j] += ar[i] * br[j];
        }
    }

    #pragma unroll
    for (int i = 0; i < 8; i++) {
        int gm = bm + ty * 8 + i;
        if (gm >= M) continue;
        #pragma unroll
        for (int j = 0; j < 8; j++) {
            int gn = bn + tx * 8 + j;
            float v = acc[i][j];
            if (EPI == EPI_RAW) {
                C[(size_t)gm * ldc + gn] = v;
            } else if (EPI == EPI_RELU) {
                C[(size_t)gm * ldc + gn] = fmaxf(v + bias[gn], 0.0f);
            } else if (EPI == EPI_RES) {
                C[(size_t)gm * ldc + gn] = v + bias[gn] + extra[(size_t)gm * ldc + gn];
            } else {  // EPI_NB: tanh((acc + 64*bias) * invden[m]), remap rows
                float tv = (v + 64.0f * bias[gn]) * extra[gm];
                C[(size_t)(gm >> 1) * 256 + (size_t)(gm & 1) * 128 + gn] = tanhf(tv);
            }
        }
    }
}

// ---------------- layernorm (ddof=1 std), per row of 256 ----------------
__global__ void ln_kernel(const float* __restrict__ Z,
                          const float* __restrict__ g,
                          const float* __restrict__ bb,
                          float* __restrict__ out)
{
    __shared__ float sbuf[256];
    int r = blockIdx.x, t = threadIdx.x;
    float z = Z[(size_t)r * 256 + t];
    float mu = block_sum256(z, sbuf) * (1.0f / 256.0f);
    float d = z - mu;
    float var = block_sum256(d * d, sbuf) * (1.0f / 255.0f);
    out[(size_t)r * 256 + t] = g[t] * d / (sqrtf(var) + 1e-6f) + bb[t];
}

// ---------------- mean over 5 support rows ----------------
__global__ void mean_kernel(const float* __restrict__ Sln, float* __restrict__ sg)
{
    int t = threadIdx.x;
    float s = 0.0f;
    #pragma unroll
    for (int i = 0; i < 5; i++) s += Sln[i * 256 + t];
    sg[t] = s * 0.2f;
}

// ---------------- rvec[n] = sum_k w_hh[n][256+k] * support_g[k] ----------------
__global__ void rvec_kernel(const float* __restrict__ w_hh,
                            const float* __restrict__ sg,
                            float* __restrict__ rv)
{
    int n = blockIdx.x * 256 + threadIdx.x;  // 2048 total
    const float* w = w_hh + (size_t)n * 512 + 256;
    float s = 0.0f;
    #pragma unroll 8
    for (int k = 0; k < 256; k++) s += w[k] * sg[k];
    rv[n] = s;
}

// ---------------- LSTM cell update ----------------
__global__ void cell_kernel(const float* __restrict__ acc,
                            const float* __restrict__ xW,
                            const float* __restrict__ b_ih,
                            const float* __restrict__ b_hh,
                            const float* __restrict__ rvec,
                            float* __restrict__ c,
                            const float* __restrict__ qg,
                            float* __restrict__ h,
                            int step)
{
    int idx = blockIdx.x * 256 + threadIdx.x;  // 4096*512
    int b = idx >> 9;
    int u = idx & 511;
    size_t base = (size_t)b * 2048;
    float gi, gf, gg, go;
    if (step == 0) {  // h_r = 0: gates = xW + b_ih + b_hh
        gi = xW[base + u]        + b_ih[u]        + b_hh[u];
        gf = xW[base + 512 + u]  + b_ih[512 + u]  + b_hh[512 + u];
        gg = xW[base + 1024 + u] + b_ih[1024 + u] + b_hh[1024 + u];
        go = xW[base + 1536 + u] + b_ih[1536 + u] + b_hh[1536 + u];
    } else {
        gi = xW[base + u]        + acc[base + u]        + b_ih[u]        + b_hh[u]        + rvec[u];
        gf = xW[base + 512 + u]  + acc[base + 512 + u]  + b_ih[512 + u]  + b_hh[512 + u]  + rvec[512 + u];
        gg = xW[base + 1024 + u] + acc[base + 1024 + u] + b_ih[1024 + u] + b_hh[1024 + u] + rvec[1024 + u];
        go = xW[base + 1536 + u] + acc[base + 1536 + u] + b_ih[1536 + u] + b_hh[1536 + u] + rvec[1536 + u];
    }
    float cp = (step == 0) ? 0.0f : c[idx];
    float cn = sigf(gf) * cp + sigf(gi) * tanhf(gg);
    c[idx] = cn;
    float hc = sigf(go) * tanhf(cn);
    if (u < 256) h[(size_t)b * 256 + u] = qg[(size_t)b * 256 + u] + hc;
}

// ---------------- normalize support_g ----------------
__global__ void snorm_kernel(const float* __restrict__ sg, float* __restrict__ sn)
{
    __shared__ float sbuf[256];
    int t = threadIdx.x;
    float v = sg[t];
    float n2 = block_sum256(v * v, sbuf);
    sn[t] = v / fmaxf(sqrtf(n2), 1e-12f);
}

// ---------------- final: out[b] = (h[b]/||h[b]||) . sn ----------------
__global__ void final_kernel(const float* __restrict__ h,
                             const float* __restrict__ sn,
                             float* __restrict__ out)
{
    __shared__ float sbuf[256];
    int b = blockIdx.x, t = threadIdx.x;
    float v = h[(size_t)b * 256 + t];
    float dot = block_sum256(v * sn[t], sbuf);
    float n2  = block_sum256(v * v, sbuf);
    if (t == 0) out[b] = dot / fmaxf(sqrtf(n2), 1e-12f);
}

// ---------------- launch ----------------
extern "C" void kernel_launch(void* const* d_in, const int* in_sizes, int n_in,
                              void* d_out, int out_size)
{
    (void)in_sizes; (void)n_in; (void)out_size;
    const int*   q_l_conn = (const int*)  d_in[2];
    const int*   q_l_deg  = (const int*)  d_in[3];
    const int*   q_r_conn = (const int*)  d_in[4];
    const int*   q_r_deg  = (const int*)  d_in[5];
    const int*   s_l_conn = (const int*)  d_in[6];
    const int*   s_l_deg  = (const int*)  d_in[7];
    const int*   s_r_conn = (const int*)  d_in[8];
    const int*   s_r_deg  = (const int*)  d_in[9];
    const float* emb      = (const float*)d_in[10];
    const float* gcn_w    = (const float*)d_in[11];
    const float* gcn_bias = (const float*)d_in[12];
    const float* proj1_w  = (const float*)d_in[13];
    const float* proj1_b  = (const float*)d_in[14];
    const float* proj2_w  = (const float*)d_in[15];
    const float* proj2_b  = (const float*)d_in[16];
    const float* ln_g     = (const float*)d_in[17];
    const float* ln_b     = (const float*)d_in[18];
    const float* w_ih     = (const float*)d_in[19];
    const float* w_hh     = (const float*)d_in[20];
    const float* b_ih     = (const float*)d_in[21];
    const float* b_hh     = (const float*)d_in[22];
    float* out = (float*)d_out;

    float* S = nullptr;
    cudaGetSymbolAddress((void**)&S, g_scratch);
    float* BUFQ = S + O_BUFQ;  float* INVQ = S + O_INVQ;
    float* BUFS = S + O_BUFS;  float* INVS = S + O_INVS;
    float* QNB  = S + O_QNB;   float* SNB  = S + O_SNB;
    float* HQ   = S + O_HQ;    float* HS   = S + O_HS;
    float* ZQ   = S + O_ZQ;    float* ZS   = S + O_ZS;
    float* QG   = S + O_QG;    float* SLN  = S + O_SLN;
    float* SG   = S + O_SG;    float* SN   = S + O_SN;
    float* XW   = S + O_XW;    float* ACC  = S + O_ACC;
    float* RV   = S + O_RV;    float* C    = S + O_C;
    float* H    = S + O_H;

    // 1) gather-sums
    gather_sum_kernel<<<4096, 128>>>(q_l_conn, q_l_deg, emb, BUFQ, INVQ, 2, 0);
    gather_sum_kernel<<<4096, 128>>>(q_r_conn, q_r_deg, emb, BUFQ, INVQ, 2, 1);
    gather_sum_kernel<<<5,    128>>>(s_l_conn, s_l_deg, emb, BUFS, INVS, 2, 0);
    gather_sum_kernel<<<5,    128>>>(s_r_conn, s_r_deg, emb, BUFS, INVS, 2, 1);

    // 2) GCN matvec + tanh -> query_nb / support_nb
    gemm_tn<EPI_NB><<<dim3(1, 64), 256>>>(BUFQ, 256, gcn_w, 256, QNB, 256,
                                          8192, 128, 256, gcn_bias, INVQ);
    gemm_tn<EPI_NB><<<dim3(1, 1), 256>>>(BUFS, 256, gcn_w, 256, SNB, 256,
                                         10, 128, 256, gcn_bias, INVS);

    // 3) support encoder (S=5)
    gemm_tn<EPI_RELU><<<dim3(4, 1), 256>>>(SNB, 256, proj1_w, 256, HS, 512,
                                           5, 512, 256, proj1_b, nullptr);
    gemm_tn<EPI_RES><<<dim3(2, 1), 256>>>(HS, 512, proj2_w, 512, ZS, 256,
                                          5, 256, 512, proj2_b, SNB);
    ln_kernel<<<5, 256>>>(ZS, ln_g, ln_b, SLN);
    mean_kernel<<<1, 256>>>(SLN, SG);

    // 4) query encoder (B=4096)
    gemm_tn<EPI_RELU><<<dim3(4, 32), 256>>>(QNB, 256, proj1_w, 256, HQ, 512,
                                            4096, 512, 256, proj1_b, nullptr);
    gemm_tn<EPI_RES><<<dim3(2, 32), 256>>>(HQ, 512, proj2_w, 512, ZQ, 256,
                                           4096, 256, 512, proj2_b, QNB);
    ln_kernel<<<4096, 256>>>(ZQ, ln_g, ln_b, QG);

    // 5) LSTM recurrence
    gemm_tn<EPI_RAW><<<dim3(16, 32), 256>>>(QG, 256, w_ih, 256, XW, 2048,
                                            4096, 2048, 256, nullptr, nullptr);
    rvec_kernel<<<8, 256>>>(w_hh, SG, RV);
    cell_kernel<<<8192, 256>>>(nullptr, XW, b_ih, b_hh, RV, C, QG, H, 0);
    for (int t = 1; t < 4; t++) {
        gemm_tn<EPI_RAW><<<dim3(16, 32), 256>>>(H, 256, w_hh, 512, ACC, 2048,
                                                4096, 2048, 256, nullptr, nullptr);
        cell_kernel<<<8192, 256>>>(ACC, XW, b_ih, b_hh, RV, C, QG, H, t);
    }

    // 6) cosine similarity
    snorm_kernel<<<1, 256>>>(SG, SN);
    final_kernel<<<4096, 256>>>(H, SN, out);
}

// round 2
// speedup vs baseline: 1.0005x; 1.0005x over previous
#include <cuda_runtime.h>
#include <math.h>

// ---------------------------------------------------------------------------
// EmbedMatcher: neighbor GCN encode -> residual MLP + LayerNorm -> 4-step
// LSTM-with-support recurrence -> cosine similarity vs support vector.
//
// Key algebraic optimization: in the recurrence, h_r = [h, support_g] where
// support_g is row-invariant, so  h_r @ w_hh^T = h @ w_hh[:, :256]^T + rvec,
// rvec = w_hh[:, 256:] @ support_g  (computed once). Recurrent GEMM K: 512->256.
// ---------------------------------------------------------------------------

#define NTHREADS 256

// ---------------- scratch (no cudaMalloc allowed) ----------------
constexpr size_t N_BUFQ = 8192UL * 256;   // gather sums, query, row = b*2+side
constexpr size_t N_INVQ = 8192;
constexpr size_t N_BUFS = 16UL * 256;     // gather sums, support (10 rows used)
constexpr size_t N_INVS = 64;
constexpr size_t N_QNB  = 4096UL * 256;   // query_nb
constexpr size_t N_SNB  = 8UL * 256;      // support_nb (5 rows)
constexpr size_t N_HQ   = 4096UL * 512;
constexpr size_t N_HS   = 8UL * 512;
constexpr size_t N_ZQ   = 4096UL * 256;
constexpr size_t N_ZS   = 8UL * 256;
constexpr size_t N_QG   = 4096UL * 256;   // query_g (post-LN)
constexpr size_t N_SLN  = 8UL * 256;
constexpr size_t N_SG   = 256;            // support_g
constexpr size_t N_SN   = 256;            // normalized support_g
constexpr size_t N_XW   = 4096UL * 2048;
constexpr size_t N_ACC  = 4096UL * 2048;
constexpr size_t N_RV   = 2048;
constexpr size_t N_C    = 4096UL * 512;
constexpr size_t N_H    = 4096UL * 256;

constexpr size_t O_BUFQ = 0;
constexpr size_t O_INVQ = O_BUFQ + N_BUFQ;
constexpr size_t O_BUFS = O_INVQ + N_INVQ;
constexpr size_t O_INVS = O_BUFS + N_BUFS;
constexpr size_t O_QNB  = O_INVS + N_INVS;
constexpr size_t O_SNB  = O_QNB  + N_QNB;
constexpr size_t O_HQ   = O_SNB  + N_SNB;
constexpr size_t O_HS   = O_HQ   + N_HQ;
constexpr size_t O_ZQ   = O_HS   + N_HS;
constexpr size_t O_ZS   = O_ZQ   + N_ZQ;
constexpr size_t O_QG   = O_ZS   + N_ZS;
constexpr size_t O_SLN  = O_QG   + N_QG;
constexpr size_t O_SG   = O_SLN  + N_SLN;
constexpr size_t O_SN   = O_SG   + N_SG;
constexpr size_t O_XW   = O_SN   + N_SN;
constexpr size_t O_ACC  = O_XW   + N_XW;
constexpr size_t O_RV   = O_ACC  + N_ACC;
constexpr size_t O_C    = O_RV   + N_RV;
constexpr size_t O_H    = O_C    + N_C;
constexpr size_t SCRATCH_TOTAL = O_H + N_H;

__device__ float g_scratch[SCRATCH_TOTAL];

// ---------------- helpers ----------------
__device__ __forceinline__ float sigf(float x) { return 1.0f / (1.0f + expf(-x)); }

__device__ __forceinline__ float block_sum256(float v, float* sbuf) {
    int t = threadIdx.x;
    sbuf[t] = v;
    __syncthreads();
    #pragma unroll
    for (int s = 128; s > 0; s >>= 1) {
        if (t < s) sbuf[t] += sbuf[t + s];
        __syncthreads();
    }
    float r = sbuf[0];
    __syncthreads();
    return r;
}

// ---------------- gather + sum over 64 neighbors ----------------
// conn: (R, 64, 2) int32. Per row: sum emb[conn[n,0]][0..127] and emb[conn[n,1]].
// Output row = r*rowmul + rowoff; buf row layout [rel_sum(128) | ent_sum(128)].
__global__ void gather_sum_kernel(const int* __restrict__ conn,
                                  const int* __restrict__ deg,
                                  const float* __restrict__ emb,
                                  float* __restrict__ buf,
                                  float* __restrict__ invden,
                                  int rowmul, int rowoff)
{
    __shared__ int sc[128];
    int r = blockIdx.x;
    int t = threadIdx.x;  // 128 threads
    sc[t] = conn[r * 128 + t];
    __syncthreads();
    float s0 = 0.0f, s1 = 0.0f;
    #pragma unroll 4
    for (int n = 0; n < 64; n++) {
        s0 += __ldg(&emb[(size_t)sc[2 * n]     * 128 + t]);
        s1 += __ldg(&emb[(size_t)sc[2 * n + 1] * 128 + t]);
    }
    int row = r * rowmul + rowoff;
    buf[(size_t)row * 256 + t]       = s0;
    buf[(size_t)row * 256 + 128 + t] = s1;
    if (t == 0) invden[row] = 1.0f / (float)max(deg[r], 1);
}

// ---------------- generic "TN" SGEMM: C[m][n] = sum_k A[m][k]*B[n][k] --------
// A: (M,K) row-major lda; B: (N,K) row-major ldb (all weights stored this way).
// Tiles: 128x128x8, 8x8 per thread, 256 threads.
enum { EPI_RAW = 0, EPI_RELU = 1, EPI_RES = 2, EPI_NB = 3 };

template <int EPI>
__global__ __launch_bounds__(256, 2)
void gemm_tn(const float* __restrict__ A, int lda,
             const float* __restrict__ B, int ldb,
             float* __restrict__ C, int ldc,
             int M, int N, int K,
             const float* __restrict__ bias,
             const float* __restrict__ extra)
{
    __shared__ float As[8][132];
    __shared__ float Bs[8][132];
    const int tid  = threadIdx.x;
    const int bm   = blockIdx.y * 128;
    const int bn   = blockIdx.x * 128;
    const int lrow = tid >> 1;          // 0..127
    const int lcol = (tid & 1) << 2;    // 0 or 4
    const int ty   = tid >> 4;          // 0..15
    const int tx   = tid & 15;          // 0..15

    float acc[8][8];
    #pragma unroll
    for (int i = 0; i < 8; i++)
        #pragma unroll
        for (int j = 0; j < 8; j++) acc[i][j] = 0.0f;

    const bool arow_ok = (bm + lrow) < M;
    const float* Aptr = A + (size_t)(bm + lrow) * lda + lcol;
    const float* Bptr = B + (size_t)(bn + lrow) * ldb + lcol;  // N is mult of 128

    for (int k0 = 0; k0 < K; k0 += 8) {
        float4 av = make_float4(0.f, 0.f, 0.f, 0.f);
        if (arow_ok) av = *(const float4*)(Aptr + k0);
        float4 bv = *(const float4*)(Bptr + k0);
        __syncthreads();
        As[lcol + 0][lrow] = av.x; As[lcol + 1][lrow] = av.y;
        As[lcol + 2][lrow] = av.z; As[lcol + 3][lrow] = av.w;
        Bs[lcol + 0][lrow] = bv.x; Bs[lcol + 1][lrow] = bv.y;
        Bs[lcol + 2][lrow] = bv.z; Bs[lcol + 3][lrow] = bv.w;
        __syncthreads();
        #pragma unroll
        for (int kk = 0; kk < 8; kk++) {
            float ar[8], br[8];
            *(float4*)&ar[0] = *(const float4*)&As[kk][ty * 8];
            *(float4*)&ar[4] = *(const float4*)&As[kk][ty * 8 + 4];
            *(float4*)&br[0] = *(const float4*)&Bs[kk][tx * 8];
            *(float4*)&br[4] = *(const float4*)&Bs[kk][tx * 8 + 4];
            #pragma unroll
            for (int i = 0; i < 8; i++)
                #pragma unroll
                for (int j = 0; j < 8; j++)
                    acc[i][j] += ar[i] * br[j];
        }
    }

    #pragma unroll
    for (int i = 0; i < 8; i++) {
        int gm = bm + ty * 8 + i;
        if (gm >= M) continue;
        #pragma unroll
        for (int j = 0; j < 8; j++) {
            int gn = bn + tx * 8 + j;
            float v = acc[i][j];
            if (EPI == EPI_RAW) {
                C[(size_t)gm * ldc + gn] = v;
            } else if (EPI == EPI_RELU) {
                C[(size_t)gm * ldc + gn] = fmaxf(v + bias[gn], 0.0f);
            } else if (EPI == EPI_RES) {
                C[(size_t)gm * ldc + gn] = v + bias[gn] + extra[(size_t)gm * ldc + gn];
            } else {  // EPI_NB: tanh((acc + 64*bias) * invden[m]), remap rows
                float tv = (v + 64.0f * bias[gn]) * extra[gm];
                C[(size_t)(gm >> 1) * 256 + (size_t)(gm & 1) * 128 + gn] = tanhf(tv);
            }
        }
    }
}

// ---------------- layernorm (ddof=1 std), per row of 256 ----------------
__global__ void ln_kernel(const float* __restrict__ Z,
                          const float* __restrict__ g,
                          const float* __restrict__ bb,
                          float* __restrict__ out)
{
    __shared__ float sbuf[256];
    int r = blockIdx.x, t = threadIdx.x;
    float z = Z[(size_t)r * 256 + t];
    float mu = block_sum256(z, sbuf) * (1.0f / 256.0f);
    float d = z - mu;
    float var = block_sum256(d * d, sbuf) * (1.0f / 255.0f);
    out[(size_t)r * 256 + t] = g[t] * d / (sqrtf(var) + 1e-6f) + bb[t];
}

// ---------------- mean over 5 support rows ----------------
__global__ void mean_kernel(const float* __restrict__ Sln, float* __restrict__ sg)
{
    int t = threadIdx.x;
    float s = 0.0f;
    #pragma unroll
    for (int i = 0; i < 5; i++) s += Sln[i * 256 + t];
    sg[t] = s * 0.2f;
}

// ---------------- rvec[n] = sum_k w_hh[n][256+k] * support_g[k] ----------------
__global__ void rvec_kernel(const float* __restrict__ w_hh,
                            const float* __restrict__ sg,
                            float* __restrict__ rv)
{
    int n = blockIdx.x * 256 + threadIdx.x;  // 2048 total
    const float* w = w_hh + (size_t)n * 512 + 256;
    float s = 0.0f;
    #pragma unroll 8
    for (int k = 0; k < 256; k++) s += w[k] * sg[k];
    rv[n] = s;
}

// ---------------- LSTM cell update ----------------
__global__ void cell_kernel(const float* __restrict__ acc,
                            const float* __restrict__ xW,
                            const float* __restrict__ b_ih,
                            const float* __restrict__ b_hh,
                            const float* __restrict__ rvec,
                            float* __restrict__ c,
                            const float* __restrict__ qg,
                            float* __restrict__ h,
                            int step)
{
    int idx = blockIdx.x * 256 + threadIdx.x;  // 4096*512
    int b = idx >> 9;
    int u = idx & 511;
    size_t base = (size_t)b * 2048;
    float gi, gf, gg, go;
    if (step == 0) {  // h_r = 0: gates = xW + b_ih + b_hh
        gi = xW[base + u]        + b_ih[u]        + b_hh[u];
        gf = xW[base + 512 + u]  + b_ih[512 + u]  + b_hh[512 + u];
        gg = xW[base + 1024 + u] + b_ih[1024 + u] + b_hh[1024 + u];
        go = xW[base + 1536 + u] + b_ih[1536 + u] + b_hh[1536 + u];
    } else {
        gi = xW[base + u]        + acc[base + u]        + b_ih[u]        + b_hh[u]        + rvec[u];
        gf = xW[base + 512 + u]  + acc[base + 512 + u]  + b_ih[512 + u]  + b_hh[512 + u]  + rvec[512 + u];
        gg = xW[base + 1024 + u] + acc[base + 1024 + u] + b_ih[1024 + u] + b_hh[1024 + u] + rvec[1024 + u];
        go = xW[base + 1536 + u] + acc[base + 1536 + u] + b_ih[1536 + u] + b_hh[1536 + u] + rvec[1536 + u];
    }
    float cp = (step == 0) ? 0.0f : c[idx];
    float cn = sigf(gf) * cp + sigf(gi) * tanhf(gg);
    c[idx] = cn;
    float hc = sigf(go) * tanhf(cn);
    if (u < 256) h[(size_t)b * 256 + u] = qg[(size_t)b * 256 + u] + hc;
}

// ---------------- normalize support_g ----------------
__global__ void snorm_kernel(const float* __restrict__ sg, float* __restrict__ sn)
{
    __shared__ float sbuf[256];
    int t = threadIdx.x;
    float v = sg[t];
    float n2 = block_sum256(v * v, sbuf);
    sn[t] = v / fmaxf(sqrtf(n2), 1e-12f);
}

// ---------------- final: out[b] = (h[b]/||h[b]||) . sn ----------------
__global__ void final_kernel(const float* __restrict__ h,
                             const float* __restrict__ sn,
                             float* __restrict__ out)
{
    __shared__ float sbuf[256];
    int b = blockIdx.x, t = threadIdx.x;
    float v = h[(size_t)b * 256 + t];
    float dot = block_sum256(v * sn[t], sbuf);
    float n2  = block_sum256(v * v, sbuf);
    if (t == 0) out[b] = dot / fmaxf(sqrtf(n2), 1e-12f);
}

// ---------------- launch ----------------
extern "C" void kernel_launch(void* const* d_in, const int* in_sizes, int n_in,
                              void* d_out, int out_size)
{
    (void)in_sizes; (void)n_in; (void)out_size;
    const int*   q_l_conn = (const int*)  d_in[2];
    const int*   q_l_deg  = (const int*)  d_in[3];
    const int*   q_r_conn = (const int*)  d_in[4];
    const int*   q_r_deg  = (const int*)  d_in[5];
    const int*   s_l_conn = (const int*)  d_in[6];
    const int*   s_l_deg  = (const int*)  d_in[7];
    const int*   s_r_conn = (const int*)  d_in[8];
    const int*   s_r_deg  = (const int*)  d_in[9];
    const float* emb      = (const float*)d_in[10];
    const float* gcn_w    = (const float*)d_in[11];
    const float* gcn_bias = (const float*)d_in[12];
    const float* proj1_w  = (const float*)d_in[13];
    const float* proj1_b  = (const float*)d_in[14];
    const float* proj2_w  = (const float*)d_in[15];
    const float* proj2_b  = (const float*)d_in[16];
    const float* ln_g     = (const float*)d_in[17];
    const float* ln_b     = (const float*)d_in[18];
    const float* w_ih     = (const float*)d_in[19];
    const float* w_hh     = (const float*)d_in[20];
    const float* b_ih     = (const float*)d_in[21];
    const float* b_hh     = (const float*)d_in[22];
    float* out = (float*)d_out;

    float* S = nullptr;
    cudaGetSymbolAddress((void**)&S, g_scratch);
    float* BUFQ = S + O_BUFQ;  float* INVQ = S + O_INVQ;
    float* BUFS = S + O_BUFS;  float* INVS = S + O_INVS;
    float* QNB  = S + O_QNB;   float* SNB  = S + O_SNB;
    float* HQ   = S + O_HQ;    float* HS   = S + O_HS;
    float* ZQ   = S + O_ZQ;    float* ZS   = S + O_ZS;
    float* QG   = S + O_QG;    float* SLN  = S + O_SLN;
    float* SG   = S + O_SG;    float* SN   = S + O_SN;
    float* XW   = S + O_XW;    float* ACC  = S + O_ACC;
    float* RV   = S + O_RV;    float* C    = S + O_C;
    float* H    = S + O_H;

    // 1) gather-sums
    gather_sum_kernel<<<4096, 128>>>(q_l_conn, q_l_deg, emb, BUFQ, INVQ, 2, 0);
    gather_sum_kernel<<<4096, 128>>>(q_r_conn, q_r_deg, emb, BUFQ, INVQ, 2, 1);
    gather_sum_kernel<<<5,    128>>>(s_l_conn, s_l_deg, emb, BUFS, INVS, 2, 0);
    gather_sum_kernel<<<5,    128>>>(s_r_conn, s_r_deg, emb, BUFS, INVS, 2, 1);

    // 2) GCN matvec + tanh -> query_nb / support_nb
    gemm_tn<EPI_NB><<<dim3(1, 64), 256>>>(BUFQ, 256, gcn_w, 256, QNB, 256,
                                          8192, 128, 256, gcn_bias, INVQ);
    gemm_tn<EPI_NB><<<dim3(1, 1), 256>>>(BUFS, 256, gcn_w, 256, SNB, 256,
                                         10, 128, 256, gcn_bias, INVS);

    // 3) support encoder (S=5)
    gemm_tn<EPI_RELU><<<dim3(4, 1), 256>>>(SNB, 256, proj1_w, 256, HS, 512,
                                           5, 512, 256, proj1_b, nullptr);
    gemm_tn<EPI_RES><<<dim3(2, 1), 256>>>(HS, 512, proj2_w, 512, ZS, 256,
                                          5, 256, 512, proj2_b, SNB);
    ln_kernel<<<5, 256>>>(ZS, ln_g, ln_b, SLN);
    mean_kernel<<<1, 256>>>(SLN, SG);

    // 4) query encoder (B=4096)
    gemm_tn<EPI_RELU><<<dim3(4, 32), 256>>>(QNB, 256, proj1_w, 256, HQ, 512,
                                            4096, 512, 256, proj1_b, nullptr);
    gemm_tn<EPI_RES><<<dim3(2, 32), 256>>>(HQ, 512, proj2_w, 512, ZQ, 256,
                                           4096, 256, 512, proj2_b, QNB);
    ln_kernel<<<4096, 256>>>(ZQ, ln_g, ln_b, QG);

    // 5) LSTM recurrence
    gemm_tn<EPI_RAW><<<dim3(16, 32), 256>>>(QG, 256, w_ih, 256, XW, 2048,
                                            4096, 2048, 256, nullptr, nullptr);
    rvec_kernel<<<8, 256>>>(w_hh, SG, RV);
    cell_kernel<<<8192, 256>>>(nullptr, XW, b_ih, b_hh, RV, C, QG, H, 0);
    for (int t = 1; t < 4; t++) {
        gemm_tn<EPI_RAW><<<dim3(16, 32), 256>>>(H, 256, w_hh, 512, ACC, 2048,
                                                4096, 2048, 256, nullptr, nullptr);
        cell_kernel<<<8192, 256>>>(ACC, XW, b_ih, b_hh, RV, C, QG, H, t);
    }

    // 6) cosine similarity
    snorm_kernel<<<1, 256>>>(SG, SN);
    final_kernel<<<4096, 256>>>(H, SN, out);
}

// round 3
// speedup vs baseline: 1.0010x; 1.0005x over previous
#include <cuda_runtime.h>
#include <math.h>

// ---------------------------------------------------------------------------
// EmbedMatcher: neighbor GCN encode -> residual MLP + LayerNorm -> 4-step
// LSTM-with-support recurrence -> cosine similarity vs support vector.
//
// Key algebraic optimization: in the recurrence, h_r = [h, support_g] where
// support_g is row-invariant, so  h_r @ w_hh^T = h @ w_hh[:, :256]^T + rvec,
// rvec = w_hh[:, 256:] @ support_g  (computed once). Recurrent GEMM K: 512->256.
// ---------------------------------------------------------------------------

#define NTHREADS 256

// ---------------- scratch (no cudaMalloc allowed) ----------------
constexpr size_t N_BUFQ = 8192UL * 256;   // gather sums, query, row = b*2+side
constexpr size_t N_INVQ = 8192;
constexpr size_t N_BUFS = 16UL * 256;     // gather sums, support (10 rows used)
constexpr size_t N_INVS = 64;
constexpr size_t N_QNB  = 4096UL * 256;   // query_nb
constexpr size_t N_SNB  = 8UL * 256;      // support_nb (5 rows)
constexpr size_t N_HQ   = 4096UL * 512;
constexpr size_t N_HS   = 8UL * 512;
constexpr size_t N_ZQ   = 4096UL * 256;
constexpr size_t N_ZS   = 8UL * 256;
constexpr size_t N_QG   = 4096UL * 256;   // query_g (post-LN)
constexpr size_t N_SLN  = 8UL * 256;
constexpr size_t N_SG   = 256;            // support_g
constexpr size_t N_SN   = 256;            // normalized support_g
constexpr size_t N_XW   = 4096UL * 2048;
constexpr size_t N_ACC  = 4096UL * 2048;
constexpr size_t N_RV   = 2048;
constexpr size_t N_C    = 4096UL * 512;
constexpr size_t N_H    = 4096UL * 256;

constexpr size_t O_BUFQ = 0;
constexpr size_t O_INVQ = O_BUFQ + N_BUFQ;
constexpr size_t O_BUFS = O_INVQ + N_INVQ;
constexpr size_t O_INVS = O_BUFS + N_BUFS;
constexpr size_t O_QNB  = O_INVS + N_INVS;
constexpr size_t O_SNB  = O_QNB  + N_QNB;
constexpr size_t O_HQ   = O_SNB  + N_SNB;
constexpr size_t O_HS   = O_HQ   + N_HQ;
constexpr size_t O_ZQ   = O_HS   + N_HS;
constexpr size_t O_ZS   = O_ZQ   + N_ZQ;
constexpr size_t O_QG   = O_ZS   + N_ZS;
constexpr size_t O_SLN  = O_QG   + N_QG;
constexpr size_t O_SG   = O_SLN  + N_SLN;
constexpr size_t O_SN   = O_SG   + N_SG;
constexpr size_t O_XW   = O_SN   + N_SN;
constexpr size_t O_ACC  = O_XW   + N_XW;
constexpr size_t O_RV   = O_ACC  + N_ACC;
constexpr size_t O_C    = O_RV   + N_RV;
constexpr size_t O_H    = O_C    + N_C;
constexpr size_t SCRATCH_TOTAL = O_H + N_H;

__device__ float g_scratch[SCRATCH_TOTAL];

// ---------------- helpers ----------------
__device__ __forceinline__ float sigf(float x) { return 1.0f / (1.0f + expf(-x)); }

__device__ __forceinline__ float block_sum256(float v, float* sbuf) {
    int t = threadIdx.x;
    sbuf[t] = v;
    __syncthreads();
    #pragma unroll
    for (int s = 128; s > 0; s >>= 1) {
        if (t < s) sbuf[t] += sbuf[t + s];
        __syncthreads();
    }
    float r = sbuf[0];
    __syncthreads();
    return r;
}

// ---------------- gather + sum over 64 neighbors ----------------
// conn: (R, 64, 2) int32. Per row: sum emb[conn[n,0]][0..127] and emb[conn[n,1]].
// Output row = r*rowmul + rowoff; buf row layout [rel_sum(128) | ent_sum(128)].
__global__ void gather_sum_kernel(const int* __restrict__ conn,
                                  const int* __restrict__ deg,
                                  const float* __restrict__ emb,
                                  float* __restrict__ buf,
                                  float* __restrict__ invden,
                                  int rowmul, int rowoff)
{
    __shared__ int sc[128];
    int r = blockIdx.x;
    int t = threadIdx.x;  // 128 threads
    sc[t] = conn[r * 128 + t];
    __syncthreads();
    float s0 = 0.0f, s1 = 0.0f;
    #pragma unroll 4
    for (int n = 0; n < 64; n++) {
        s0 += __ldg(&emb[(size_t)sc[2 * n]     * 128 + t]);
        s1 += __ldg(&emb[(size_t)sc[2 * n + 1] * 128 + t]);
    }
    int row = r * rowmul + rowoff;
    buf[(size_t)row * 256 + t]       = s0;
    buf[(size_t)row * 256 + 128 + t] = s1;
    if (t == 0) invden[row] = 1.0f / (float)max(deg[r], 1);
}

// ---------------- generic "TN" SGEMM: C[m][n] = sum_k A[m][k]*B[n][k] --------
// A: (M,K) row-major lda; B: (N,K) row-major ldb (all weights stored this way).
// Tiles: 128x128x8, 8x8 per thread, 256 threads.
enum { EPI_RAW = 0, EPI_RELU = 1, EPI_RES = 2, EPI_NB = 3 };

template <int EPI>
__global__ __launch_bounds__(256, 2)
void gemm_tn(const float* __restrict__ A, int lda,
             const float* __restrict__ B, int ldb,
             float* __restrict__ C, int ldc,
             int M, int N, int K,
             const float* __restrict__ bias,
             const float* __restrict__ extra)
{
    __shared__ float As[8][132];
    __shared__ float Bs[8][132];
    const int tid  = threadIdx.x;
    const int bm   = blockIdx.y * 128;
    const int bn   = blockIdx.x * 128;
    const int lrow = tid >> 1;          // 0..127
    const int lcol = (tid & 1) << 2;    // 0 or 4
    const int ty   = tid >> 4;          // 0..15
    const int tx   = tid & 15;          // 0..15

    float acc[8][8];
    #pragma unroll
    for (int i = 0; i < 8; i++)
        #pragma unroll
        for (int j = 0; j < 8; j++) acc[i][j] = 0.0f;

    const bool arow_ok = (bm + lrow) < M;
    const float* Aptr = A + (size_t)(bm + lrow) * lda + lcol;
    const float* Bptr = B + (size_t)(bn + lrow) * ldb + lcol;  // N is mult of 128

    for (int k0 = 0; k0 < K; k0 += 8) {
        float4 av = make_float4(0.f, 0.f, 0.f, 0.f);
        if (arow_ok) av = *(const float4*)(Aptr + k0);
        float4 bv = *(const float4*)(Bptr + k0);
        __syncthreads();
        As[lcol + 0][lrow] = av.x; As[lcol + 1][lrow] = av.y;
        As[lcol + 2][lrow] = av.z; As[lcol + 3][lrow] = av.w;
        Bs[lcol + 0][lrow] = bv.x; Bs[lcol + 1][lrow] = bv.y;
        Bs[lcol + 2][lrow] = bv.z; Bs[lcol + 3][lrow] = bv.w;
        __syncthreads();
        #pragma unroll
        for (int kk = 0; kk < 8; kk++) {
            float ar[8], br[8];
            *(float4*)&ar[0] = *(const float4*)&As[kk][ty * 8];
            *(float4*)&ar[4] = *(const float4*)&As[kk][ty * 8 + 4];
            *(float4*)&br[0] = *(const float4*)&Bs[kk][tx * 8];
            *(float4*)&br[4] = *(const float4*)&Bs[kk][tx * 8 + 4];
            #pragma unroll
            for (int i = 0; i < 8; i++)
                #pragma unroll
                for (int j = 0; j < 8; j++)
                    acc[i][j] += ar[i] * br[j];
        }
    }

    #pragma unroll
    for (int i = 0; i < 8; i++) {
        int gm = bm + ty * 8 + i;
        if (gm >= M) continue;
        #pragma unroll
        for (int j = 0; j < 8; j++) {
            int gn = bn + tx * 8 + j;
            float v = acc[i][j];
            if (EPI == EPI_RAW) {
                C[(size_t)gm * ldc + gn] = v;
            } else if (EPI == EPI_RELU) {
                C[(size_t)gm * ldc + gn] = fmaxf(v + bias[gn], 0.0f);
            } else if (EPI == EPI_RES) {
                C[(size_t)gm * ldc + gn] = v + bias[gn] + extra[(size_t)gm * ldc + gn];
            } else {  // EPI_NB: tanh((acc + 64*bias) * invden[m]), remap rows
                float tv = (v + 64.0f * bias[gn]) * extra[gm];
                C[(size_t)(gm >> 1) * 256 + (size_t)(gm & 1) * 128 + gn] = tanhf(tv);
            }
        }
    }
}

// ---------------- layernorm (ddof=1 std), per row of 256 ----------------
__global__ void ln_kernel(const float* __restrict__ Z,
                          const float* __restrict__ g,
                          const float* __restrict__ bb,
                          float* __restrict__ out)
{
    __shared__ float sbuf[256];
    int r = blockIdx.x, t = threadIdx.x;
    float z = Z[(size_t)r * 256 + t];
    float mu = block_sum256(z, sbuf) * (1.0f / 256.0f);
    float d = z - mu;
    float var = block_sum256(d * d, sbuf) * (1.0f / 255.0f);
    out[(size_t)r * 256 + t] = g[t] * d / (sqrtf(var) + 1e-6f) + bb[t];
}

// ---------------- mean over 5 support rows ----------------
__global__ void mean_kernel(const float* __restrict__ Sln, float* __restrict__ sg)
{
    int t = threadIdx.x;
    float s = 0.0f;
    #pragma unroll
    for (int i = 0; i < 5; i++) s += Sln[i * 256 + t];
    sg[t] = s * 0.2f;
}

// ---------------- rvec[n] = sum_k w_hh[n][256+k] * support_g[k] ----------------
__global__ void rvec_kernel(const float* __restrict__ w_hh,
                            const float* __restrict__ sg,
                            float* __restrict__ rv)
{
    int n = blockIdx.x * 256 + threadIdx.x;  // 2048 total
    const float* w = w_hh + (size_t)n * 512 + 256;
    float s = 0.0f;
    #pragma unroll 8
    for (int k = 0; k < 256; k++) s += w[k] * sg[k];
    rv[n] = s;
}

// ---------------- LSTM cell update ----------------
__global__ void cell_kernel(const float* __restrict__ acc,
                            const float* __restrict__ xW,
                            const float* __restrict__ b_ih,
                            const float* __restrict__ b_hh,
                            const float* __restrict__ rvec,
                            float* __restrict__ c,
                            const float* __restrict__ qg,
                            float* __restrict__ h,
                            int step)
{
    int idx = blockIdx.x * 256 + threadIdx.x;  // 4096*512
    int b = idx >> 9;
    int u = idx & 511;
    size_t base = (size_t)b * 2048;
    float gi, gf, gg, go;
    if (step == 0) {  // h_r = 0: gates = xW + b_ih + b_hh
        gi = xW[base + u]        + b_ih[u]        + b_hh[u];
        gf = xW[base + 512 + u]  + b_ih[512 + u]  + b_hh[512 + u];
        gg = xW[base + 1024 + u] + b_ih[1024 + u] + b_hh[1024 + u];
        go = xW[base + 1536 + u] + b_ih[1536 + u] + b_hh[1536 + u];
    } else {
        gi = xW[base + u]        + acc[base + u]        + b_ih[u]        + b_hh[u]        + rvec[u];
        gf = xW[base + 512 + u]  + acc[base + 512 + u]  + b_ih[512 + u]  + b_hh[512 + u]  + rvec[512 + u];
        gg = xW[base + 1024 + u] + acc[base + 1024 + u] + b_ih[1024 + u] + b_hh[1024 + u] + rvec[1024 + u];
        go = xW[base + 1536 + u] + acc[base + 1536 + u] + b_ih[1536 + u] + b_hh[1536 + u] + rvec[1536 + u];
    }
    float cp = (step == 0) ? 0.0f : c[idx];
    float cn = sigf(gf) * cp + sigf(gi) * tanhf(gg);
    c[idx] = cn;
    float hc = sigf(go) * tanhf(cn);
    if (u < 256) h[(size_t)b * 256 + u] = qg[(size_t)b * 256 + u] + hc;
}

// ---------------- normalize support_g ----------------
__global__ void snorm_kernel(const float* __restrict__ sg, float* __restrict__ sn)
{
    __shared__ float sbuf[256];
    int t = threadIdx.x;
    float v = sg[t];
    float n2 = block_sum256(v * v, sbuf);
    sn[t] = v / fmaxf(sqrtf(n2), 1e-12f);
}

// ---------------- final: out[b] = (h[b]/||h[b]||) . sn ----------------
__global__ void final_kernel(const float* __restrict__ h,
                             const float* __restrict__ sn,
                             float* __restrict__ out)
{
    __shared__ float sbuf[256];
    int b = blockIdx.x, t = threadIdx.x;
    float v = h[(size_t)b * 256 + t];
    float dot = block_sum256(v * sn[t], sbuf);
    float n2  = block_sum256(v * v, sbuf);
    if (t == 0) out[b] = dot / fmaxf(sqrtf(n2), 1e-12f);
}

// ---------------- launch ----------------
extern "C" void kernel_launch(void* const* d_in, const int* in_sizes, int n_in,
                              void* d_out, int out_size)
{
    (void)in_sizes; (void)n_in; (void)out_size;
    const int*   q_l_conn = (const int*)  d_in[2];
    const int*   q_l_deg  = (const int*)  d_in[3];
    const int*   q_r_conn = (const int*)  d_in[4];
    const int*   q_r_deg  = (const int*)  d_in[5];
    const int*   s_l_conn = (const int*)  d_in[6];
    const int*   s_l_deg  = (const int*)  d_in[7];
    const int*   s_r_conn = (const int*)  d_in[8];
    const int*   s_r_deg  = (const int*)  d_in[9];
    const float* emb      = (const float*)d_in[10];
    const float* gcn_w    = (const float*)d_in[11];
    const float* gcn_bias = (const float*)d_in[12];
    const float* proj1_w  = (const float*)d_in[13];
    const float* proj1_b  = (const float*)d_in[14];
    const float* proj2_w  = (const float*)d_in[15];
    const float* proj2_b  = (const float*)d_in[16];
    const float* ln_g     = (const float*)d_in[17];
    const float* ln_b     = (const float*)d_in[18];
    const float* w_ih     = (const float*)d_in[19];
    const float* w_hh     = (const float*)d_in[20];
    const float* b_ih     = (const float*)d_in[21];
    const float* b_hh     = (const float*)d_in[22];
    float* out = (float*)d_out;

    float* S = nullptr;
    cudaGetSymbolAddress((void**)&S, g_scratch);
    float* BUFQ = S + O_BUFQ;  float* INVQ = S + O_INVQ;
    float* BUFS = S + O_BUFS;  float* INVS = S + O_INVS;
    float* QNB  = S + O_QNB;   float* SNB  = S + O_SNB;
    float* HQ   = S + O_HQ;    float* HS   = S + O_HS;
    float* ZQ   = S + O_ZQ;    float* ZS   = S + O_ZS;
    float* QG   = S + O_QG;    float* SLN  = S + O_SLN;
    float* SG   = S + O_SG;    float* SN   = S + O_SN;
    float* XW   = S + O_XW;    float* ACC  = S + O_ACC;
    float* RV   = S + O_RV;    float* C    = S + O_C;
    float* H    = S + O_H;

    // 1) gather-sums
    gather_sum_kernel<<<4096, 128>>>(q_l_conn, q_l_deg, emb, BUFQ, INVQ, 2, 0);
    gather_sum_kernel<<<4096, 128>>>(q_r_conn, q_r_deg, emb, BUFQ, INVQ, 2, 1);
    gather_sum_kernel<<<5,    128>>>(s_l_conn, s_l_deg, emb, BUFS, INVS, 2, 0);
    gather_sum_kernel<<<5,    128>>>(s_r_conn, s_r_deg, emb, BUFS, INVS, 2, 1);

    // 2) GCN matvec + tanh -> query_nb / support_nb
    gemm_tn<EPI_NB><<<dim3(1, 64), 256>>>(BUFQ, 256, gcn_w, 256, QNB, 256,
                                          8192, 128, 256, gcn_bias, INVQ);
    gemm_tn<EPI_NB><<<dim3(1, 1), 256>>>(BUFS, 256, gcn_w, 256, SNB, 256,
                                         10, 128, 256, gcn_bias, INVS);

    // 3) support encoder (S=5)
    gemm_tn<EPI_RELU><<<dim3(4, 1), 256>>>(SNB, 256, proj1_w, 256, HS, 512,
                                           5, 512, 256, proj1_b, nullptr);
    gemm_tn<EPI_RES><<<dim3(2, 1), 256>>>(HS, 512, proj2_w, 512, ZS, 256,
                                          5, 256, 512, proj2_b, SNB);
    ln_kernel<<<5, 256>>>(ZS, ln_g, ln_b, SLN);
    mean_kernel<<<1, 256>>>(SLN, SG);

    // 4) query encoder (B=4096)
    gemm_tn<EPI_RELU><<<dim3(4, 32), 256>>>(QNB, 256, proj1_w, 256, HQ, 512,
                                            4096, 512, 256, proj1_b, nullptr);
    gemm_tn<EPI_RES><<<dim3(2, 32), 256>>>(HQ, 512, proj2_w, 512, ZQ, 256,
                                           4096, 256, 512, proj2_b, QNB);
    ln_kernel<<<4096, 256>>>(ZQ, ln_g, ln_b, QG);

    // 5) LSTM recurrence
    gemm_tn<EPI_RAW><<<dim3(16, 32), 256>>>(QG, 256, w_ih, 256, XW, 2048,
                                            4096, 2048, 256, nullptr, nullptr);
    rvec_kernel<<<8, 256>>>(w_hh, SG, RV);
    cell_kernel<<<8192, 256>>>(nullptr, XW, b_ih, b_hh, RV, C, QG, H, 0);
    for (int t = 1; t < 4; t++) {
        gemm_tn<EPI_RAW><<<dim3(16, 32), 256>>>(H, 256, w_hh, 512, ACC, 2048,
                                                4096, 2048, 256, nullptr, nullptr);
        cell_kernel<<<8192, 256>>>(ACC, XW, b_ih, b_hh, RV, C, QG, H, t);
    }

    // 6) cosine similarity
    snorm_kernel<<<1, 256>>>(SG, SN);
    final_kernel<<<4096, 256>>>(H, SN, out);
}